// round 3
// baseline (speedup 1.0000x reference)
#include <cuda_runtime.h>
#include <math.h>

#define HD 1024
#define VV 50257
#define SS 4096
#define GG 3072   // 3*H

// ---- scratch (no allocations allowed) ----
__device__ float g_gi[GG];
__device__ float g_gh[GG];
__device__ float g_hnew[HD];
__device__ float g_scores[SS];
__device__ float g_logits[VV];
__device__ float g_cpart[32 * HD];
__device__ float g_lse[1];

__device__ __forceinline__ float warp_sum(float v) {
#pragma unroll
    for (int o = 16; o > 0; o >>= 1) v += __shfl_down_sync(0xffffffffu, v, o);
    return v;
}

// ---------------------------------------------------------------------------
// K1: gi = w_ih @ [emb(word); last_ctx] + b_ih ; gh = w_hh @ h + b_hh
// one warp per output row (3072 rows), 8 warps/block
// ---------------------------------------------------------------------------
__global__ void __launch_bounds__(256)
k_gates(const int* __restrict__ word,
        const float* __restrict__ last_ctx,
        const float* __restrict__ last_hid,
        const float* __restrict__ emb,
        const float* __restrict__ w_ih,
        const float* __restrict__ w_hh,
        const float* __restrict__ b_ih,
        const float* __restrict__ b_hh) {
    __shared__ float sx[2 * HD];
    __shared__ float sh[HD];
    const int t = threadIdx.x;
    const int w = word[0];
    for (int i = t; i < HD; i += blockDim.x) {
        sx[i]      = emb[(size_t)w * HD + i];
        sx[HD + i] = last_ctx[i];
        sh[i]      = last_hid[i];
    }
    __syncthreads();

    const int lane = t & 31;
    const int row  = blockIdx.x * 8 + (t >> 5);
    if (row >= GG) return;

    const float4* wi4 = (const float4*)(w_ih + (size_t)row * 2 * HD);
    const float4* wh4 = (const float4*)(w_hh + (size_t)row * HD);
    const float4* sx4 = (const float4*)sx;
    const float4* sh4 = (const float4*)sh;

    float si = 0.f, sg = 0.f;
#pragma unroll 16
    for (int j = lane; j < 512; j += 32) {
        float4 a = wi4[j], b = sx4[j];
        si += a.x * b.x + a.y * b.y + a.z * b.z + a.w * b.w;
    }
#pragma unroll 8
    for (int j = lane; j < 256; j += 32) {
        float4 a = wh4[j], b = sh4[j];
        sg += a.x * b.x + a.y * b.y + a.z * b.z + a.w * b.w;
    }
    si = warp_sum(si);
    sg = warp_sum(sg);
    if (lane == 0) {
        g_gi[row] = si + b_ih[row];
        g_gh[row] = sg + b_hh[row];
    }
}

// ---------------------------------------------------------------------------
// K2: GRU nonlinearity -> h_new   (1 block, 1024 threads)
// ---------------------------------------------------------------------------
__global__ void k_hnew(const float* __restrict__ last_hid,
                       float* __restrict__ o_hnew) {
    const int i = threadIdx.x;
    float r = 1.f / (1.f + expf(-(g_gi[i] + g_gh[i])));
    float z = 1.f / (1.f + expf(-(g_gi[HD + i] + g_gh[HD + i])));
    float n = tanhf(g_gi[2 * HD + i] + r * g_gh[2 * HD + i]);
    float h = last_hid[i];
    float hn = (1.f - z) * n + z * h;
    g_hnew[i] = hn;
    o_hnew[i] = hn;
}

// ---------------------------------------------------------------------------
// K3: scores[s] = enc[s,:] . h_new   (warp per s)
// ---------------------------------------------------------------------------
__global__ void __launch_bounds__(256)
k_scores(const float* __restrict__ enc) {
    __shared__ float sh[HD];
    const int t = threadIdx.x;
    for (int i = t; i < HD; i += blockDim.x) sh[i] = g_hnew[i];
    __syncthreads();

    const int lane = t & 31;
    const int s    = blockIdx.x * 8 + (t >> 5);
    if (s >= SS) return;
    const float4* e4 = (const float4*)(enc + (size_t)s * HD);
    const float4* h4 = (const float4*)sh;
    float acc = 0.f;
#pragma unroll 8
    for (int j = lane; j < 256; j += 32) {
        float4 a = e4[j], b = h4[j];
        acc += a.x * b.x + a.y * b.y + a.z * b.z + a.w * b.w;
    }
    acc = warp_sum(acc);
    if (lane == 0) g_scores[s] = acc;
}

// ---------------------------------------------------------------------------
// K4: softmax over 4096 scores -> attn (in d_out)
// 1 block, 1024 threads (4 elems each)
// ---------------------------------------------------------------------------
__global__ void k_softmax(float* __restrict__ o_attn) {
    __shared__ float red[32];
    const int t = threadIdx.x;
    float v[4];
    float m = -INFINITY;
#pragma unroll
    for (int k = 0; k < 4; k++) {
        v[k] = g_scores[t + k * 1024];
        m = fmaxf(m, v[k]);
    }
#pragma unroll
    for (int o = 16; o > 0; o >>= 1) m = fmaxf(m, __shfl_down_sync(0xffffffffu, m, o));
    if ((t & 31) == 0) red[t >> 5] = m;
    __syncthreads();
    if (t < 32) {
        float mm = red[t];
#pragma unroll
        for (int o = 16; o > 0; o >>= 1) mm = fmaxf(mm, __shfl_down_sync(0xffffffffu, mm, o));
        if (t == 0) red[0] = mm;
    }
    __syncthreads();
    m = red[0];
    __syncthreads();

    float e[4];
    float s = 0.f;
#pragma unroll
    for (int k = 0; k < 4; k++) {
        e[k] = expf(v[k] - m);
        s += e[k];
    }
    s = warp_sum(s);
    if ((t & 31) == 0) red[t >> 5] = s;
    __syncthreads();
    if (t < 32) {
        float ss = red[t];
        ss = warp_sum(ss);
        if (t == 0) red[0] = ss;
    }
    __syncthreads();
    const float inv = 1.f / red[0];
#pragma unroll
    for (int k = 0; k < 4; k++) o_attn[t + k * 1024] = e[k] * inv;
}

// ---------------------------------------------------------------------------
// K5: context partials: block b sums attn[s]*enc[s,:] over its s-chunk
// 32 blocks x 256 threads, thread owns one float4 column group
// ---------------------------------------------------------------------------
__global__ void __launch_bounds__(256)
k_ctx_part(const float* __restrict__ enc,
           const float* __restrict__ o_attn) {
    const int t = threadIdx.x;          // 0..255  -> float4 index
    const int b = blockIdx.x;           // 0..31
    const int s0 = b * (SS / 32);
    float4 acc = make_float4(0.f, 0.f, 0.f, 0.f);
    const float4* e4 = (const float4*)enc;
    for (int s = s0; s < s0 + SS / 32; s++) {
        const float a = o_attn[s];
        float4 e = e4[(size_t)s * 256 + t];
        acc.x += a * e.x; acc.y += a * e.y; acc.z += a * e.z; acc.w += a * e.w;
    }
    ((float4*)(g_cpart + (size_t)b * HD))[t] = acc;
}

// K5b: reduce 32 partials -> context (1 block, 1024 threads)
__global__ void k_ctx_reduce(float* __restrict__ o_ctx) {
    const int j = threadIdx.x;
    float s = 0.f;
#pragma unroll
    for (int b = 0; b < 32; b++) s += g_cpart[b * HD + j];
    o_ctx[j] = s;
}

// ---------------------------------------------------------------------------
// K6: logits = out_w @ [h_new ; context] + out_b   (warp per row, 50257 rows)
// ---------------------------------------------------------------------------
__global__ void __launch_bounds__(256)
k_logits(const float* __restrict__ out_w,
         const float* __restrict__ out_b,
         const float* __restrict__ o_ctx) {
    __shared__ float sx[2 * HD];
    const int t = threadIdx.x;
    for (int i = t; i < HD; i += blockDim.x) {
        sx[i]      = g_hnew[i];
        sx[HD + i] = o_ctx[i];
    }
    __syncthreads();

    const int lane = t & 31;
    const int row  = blockIdx.x * 8 + (t >> 5);
    if (row >= VV) return;

    const float4* w4  = (const float4*)(out_w + (size_t)row * 2 * HD);
    const float4* sx4 = (const float4*)sx;
    float acc = 0.f;
#pragma unroll 16
    for (int j = lane; j < 512; j += 32) {
        float4 a = w4[j], b = sx4[j];
        acc += a.x * b.x + a.y * b.y + a.z * b.z + a.w * b.w;
    }
    acc = warp_sum(acc);
    if (lane == 0) g_logits[row] = acc + out_b[row];
}

// ---------------------------------------------------------------------------
// K7: lse = max + log(sum exp(l - max))   (1 block, 1024 threads)
// ---------------------------------------------------------------------------
__global__ void k_lse() {
    __shared__ float red[32];
    const int t = threadIdx.x;
    float m = -INFINITY;
    for (int i = t; i < VV; i += 1024) m = fmaxf(m, g_logits[i]);
#pragma unroll
    for (int o = 16; o > 0; o >>= 1) m = fmaxf(m, __shfl_down_sync(0xffffffffu, m, o));
    if ((t & 31) == 0) red[t >> 5] = m;
    __syncthreads();
    if (t < 32) {
        float mm = red[t];
#pragma unroll
        for (int o = 16; o > 0; o >>= 1) mm = fmaxf(mm, __shfl_down_sync(0xffffffffu, mm, o));
        if (t == 0) red[0] = mm;
    }
    __syncthreads();
    m = red[0];
    __syncthreads();

    float s = 0.f;
    for (int i = t; i < VV; i += 1024) s += expf(g_logits[i] - m);
    s = warp_sum(s);
    if ((t & 31) == 0) red[t >> 5] = s;
    __syncthreads();
    if (t < 32) {
        float ss = red[t];
        ss = warp_sum(ss);
        if (t == 0) g_lse[0] = m + logf(ss);
    }
}

// K8: output = logits - lse
__global__ void k_out(float* __restrict__ o_out) {
    const int i = blockIdx.x * blockDim.x + threadIdx.x;
    if (i < VV) o_out[i] = g_logits[i] - g_lse[0];
}

// ---------------------------------------------------------------------------
extern "C" void kernel_launch(void* const* d_in, const int* in_sizes, int n_in,
                              void* d_out, int out_size) {
    const int*   word     = (const int*)  d_in[0];
    const float* last_ctx = (const float*)d_in[1];
    const float* last_hid = (const float*)d_in[2];
    const float* enc      = (const float*)d_in[3];
    const float* emb      = (const float*)d_in[4];
    const float* w_ih     = (const float*)d_in[5];
    const float* w_hh     = (const float*)d_in[6];
    const float* b_ih     = (const float*)d_in[7];
    const float* b_hh     = (const float*)d_in[8];
    const float* out_w    = (const float*)d_in[9];
    const float* out_b    = (const float*)d_in[10];

    float* out    = (float*)d_out;
    float* o_out  = out;                 // [V]   log_softmax output
    float* o_ctx  = out + VV;            // [H]   context
    float* o_hn   = out + VV + HD;       // [H]   h_new
    float* o_attn = out + VV + 2 * HD;   // [S]   attn

    k_gates<<<GG / 8, 256>>>(word, last_ctx, last_hid, emb, w_ih, w_hh, b_ih, b_hh);
    k_hnew<<<1, HD>>>(last_hid, o_hn);
    k_scores<<<SS / 8, 256>>>(enc);
    k_softmax<<<1, 1024>>>(o_attn);
    k_ctx_part<<<32, 256>>>(enc, o_attn);
    k_ctx_reduce<<<1, HD>>>(o_ctx);
    k_logits<<<(VV + 7) / 8, 256>>>(out_w, out_b, o_ctx);
    k_lse<<<1, 1024>>>();
    k_out<<<(VV + 255) / 256, 256>>>(o_out);
}

// round 9
// speedup vs baseline: 1.0571x; 1.0571x over previous
#include <cuda_runtime.h>
#include <math.h>

#define HD 1024
#define VV 50257
#define SS 4096
#define GG 3072   // 3*H

// ---- scratch (no allocations allowed) ----
__device__ float g_gi[GG];
__device__ float g_gh[GG];
__device__ float g_hnew[HD];
__device__ float g_scores[SS];
__device__ float g_logits[VV];
__device__ float g_cpart[32 * HD];

__device__ __forceinline__ float warp_sum(float v) {
#pragma unroll
    for (int o = 16; o > 0; o >>= 1) v += __shfl_down_sync(0xffffffffu, v, o);
    return v;
}
__device__ __forceinline__ float warp_max(float v) {
#pragma unroll
    for (int o = 16; o > 0; o >>= 1) v = fmaxf(v, __shfl_down_sync(0xffffffffu, v, o));
    return v;
}

// ---------------------------------------------------------------------------
// K1: gi = w_ih @ [emb(word); last_ctx] + b_ih ; gh = w_hh @ h + b_hh
// one warp per output row (3072 rows), 8 warps/block
// ---------------------------------------------------------------------------
__global__ void __launch_bounds__(256)
k_gates(const int* __restrict__ word,
        const float* __restrict__ last_ctx,
        const float* __restrict__ last_hid,
        const float* __restrict__ emb,
        const float* __restrict__ w_ih,
        const float* __restrict__ w_hh,
        const float* __restrict__ b_ih,
        const float* __restrict__ b_hh) {
    __shared__ float sx[2 * HD];
    __shared__ float sh[HD];
    const int t = threadIdx.x;
    const int w = word[0];
    for (int i = t; i < HD; i += blockDim.x) {
        sx[i]      = emb[(size_t)w * HD + i];
        sx[HD + i] = last_ctx[i];
        sh[i]      = last_hid[i];
    }
    __syncthreads();

    const int lane = t & 31;
    const int row  = blockIdx.x * 8 + (t >> 5);

    const float4* wi4 = (const float4*)(w_ih + (size_t)row * 2 * HD);
    const float4* wh4 = (const float4*)(w_hh + (size_t)row * HD);
    const float4* sx4 = (const float4*)sx;
    const float4* sh4 = (const float4*)sh;

    float si = 0.f, sg = 0.f;
#pragma unroll 16
    for (int j = lane; j < 512; j += 32) {
        float4 a = wi4[j], b = sx4[j];
        si += a.x * b.x + a.y * b.y + a.z * b.z + a.w * b.w;
    }
#pragma unroll 8
    for (int j = lane; j < 256; j += 32) {
        float4 a = wh4[j], b = sh4[j];
        sg += a.x * b.x + a.y * b.y + a.z * b.z + a.w * b.w;
    }
    si = warp_sum(si);
    sg = warp_sum(sg);
    if (lane == 0) {
        g_gi[row] = si + b_ih[row];
        g_gh[row] = sg + b_hh[row];
    }
}

// ---------------------------------------------------------------------------
// K2: each block recomputes h_new (redundant, L2-cheap), then warp-per-s
//     computes scores[s] = enc[s,:] . h_new.  128 blocks x 1024 threads.
//     Block 0 publishes g_hnew and o_hn.
// ---------------------------------------------------------------------------
__global__ void __launch_bounds__(1024)
k_hnew_scores(const float* __restrict__ last_hid,
              const float* __restrict__ enc,
              float* __restrict__ o_hn) {
    __shared__ float sh[HD];
    const int t = threadIdx.x;

    // h_new (every block; identical values)
    {
        float r = 1.f / (1.f + expf(-(g_gi[t] + g_gh[t])));
        float z = 1.f / (1.f + expf(-(g_gi[HD + t] + g_gh[HD + t])));
        float n = tanhf(g_gi[2 * HD + t] + r * g_gh[2 * HD + t]);
        float h = last_hid[t];
        float hn = (1.f - z) * n + z * h;
        sh[t] = hn;
        if (blockIdx.x == 0) {
            g_hnew[t] = hn;
            o_hn[t]   = hn;
        }
    }
    __syncthreads();

    const int lane = t & 31;
    const int s    = blockIdx.x * 32 + (t >> 5);
    const float4* e4 = (const float4*)(enc + (size_t)s * HD);
    const float4* h4 = (const float4*)sh;
    float acc = 0.f;
#pragma unroll 8
    for (int j = lane; j < 256; j += 32) {
        float4 a = e4[j], b = h4[j];
        acc += a.x * b.x + a.y * b.y + a.z * b.z + a.w * b.w;
    }
    acc = warp_sum(acc);
    if (lane == 0) g_scores[s] = acc;
}

// ---------------------------------------------------------------------------
// K3: fused softmax + context partials.  32 blocks x 256 threads.
//     Each block redundantly computes global max/sum over all 4096 scores,
//     writes its attn slice (128 rows), accumulates its ctx partial.
// ---------------------------------------------------------------------------
__global__ void __launch_bounds__(256)
k_attn_ctx(const float* __restrict__ enc,
           float* __restrict__ o_attn) {
    __shared__ float ss[SS];       // all scores
    __shared__ float red[32];
    __shared__ float sattn[128];   // this block's attn chunk
    const int t = threadIdx.x;
    const int b = blockIdx.x;

    // load all scores, track max
    float m = -INFINITY;
    float4* ss4 = (float4*)ss;
    const float4* gs4 = (const float4*)g_scores;
#pragma unroll
    for (int k = 0; k < 4; k++) {
        float4 v = gs4[t + k * 256];
        ss4[t + k * 256] = v;
        m = fmaxf(m, fmaxf(fmaxf(v.x, v.y), fmaxf(v.z, v.w)));
    }
    m = warp_max(m);
    if ((t & 31) == 0) red[t >> 5] = m;
    __syncthreads();
    if (t < 32) {
        float mm = (t < 8) ? red[t] : -INFINITY;
        mm = warp_max(mm);
        if (t == 0) red[0] = mm;
    }
    __syncthreads();
    m = red[0];
    __syncthreads();

    // global sum of exp
    float s = 0.f;
    for (int i = t; i < SS; i += 256) s += expf(ss[i] - m);
    s = warp_sum(s);
    if ((t & 31) == 0) red[t >> 5] = s;
    __syncthreads();
    if (t < 32) {
        float sv = (t < 8) ? red[t] : 0.f;
        sv = warp_sum(sv);
        if (t == 0) red[0] = sv;
    }
    __syncthreads();
    const float inv = 1.f / red[0];

    // this block's attn slice
    const int s0 = b * 128;
    if (t < 128) {
        float a = expf(ss[s0 + t] - m) * inv;
        sattn[t]      = a;
        o_attn[s0 + t] = a;
    }
    __syncthreads();

    // ctx partial: thread t owns float4 column group
    float4 acc = make_float4(0.f, 0.f, 0.f, 0.f);
    const float4* e4 = (const float4*)enc;
    for (int k = 0; k < 128; k++) {
        const float a = sattn[k];
        float4 e = e4[(size_t)(s0 + k) * 256 + t];
        acc.x += a * e.x; acc.y += a * e.y; acc.z += a * e.z; acc.w += a * e.w;
    }
    ((float4*)(g_cpart + (size_t)b * HD))[t] = acc;
}

// K4: reduce 32 partials -> context (1 block, 1024 threads)
__global__ void k_ctx_reduce(float* __restrict__ o_ctx) {
    const int j = threadIdx.x;
    float s = 0.f;
#pragma unroll
    for (int b = 0; b < 32; b++) s += g_cpart[b * HD + j];
    o_ctx[j] = s;
}

// ---------------------------------------------------------------------------
// K5: logits = out_w @ [h_new ; context] + out_b   (warp per row, 50257 rows)
// ---------------------------------------------------------------------------
__global__ void __launch_bounds__(256)
k_logits(const float* __restrict__ out_w,
         const float* __restrict__ out_b,
         const float* __restrict__ o_ctx) {
    __shared__ float sx[2 * HD];
    const int t = threadIdx.x;
    for (int i = t; i < HD; i += blockDim.x) {
        sx[i]      = g_hnew[i];
        sx[HD + i] = o_ctx[i];
    }
    __syncthreads();

    const int lane = t & 31;
    const int row  = blockIdx.x * 8 + (t >> 5);
    if (row >= VV) return;

    const float4* w4  = (const float4*)(out_w + (size_t)row * 2 * HD);
    const float4* sx4 = (const float4*)sx;
    float acc = 0.f;
#pragma unroll 16
    for (int j = lane; j < 512; j += 32) {
        float4 a = w4[j], b = sx4[j];
        acc += a.x * b.x + a.y * b.y + a.z * b.z + a.w * b.w;
    }
    acc = warp_sum(acc);
    if (lane == 0) g_logits[row] = acc + out_b[row];
}

// ---------------------------------------------------------------------------
// K6: fused log-sum-exp + output.  32 blocks x 1024 threads.
//     Each block redundantly reduces over all 50257 logits (L2-resident),
//     then writes its strided slice of the output.
// ---------------------------------------------------------------------------
__global__ void __launch_bounds__(1024)
k_lse_out(float* __restrict__ o_out) {
    __shared__ float red[32];
    const int t = threadIdx.x;

    float m = -INFINITY;
    for (int i = t; i < VV; i += 1024) m = fmaxf(m, g_logits[i]);
    m = warp_max(m);
    if ((t & 31) == 0) red[t >> 5] = m;
    __syncthreads();
    if (t < 32) {
        float mm = red[t];
        mm = warp_max(mm);
        if (t == 0) red[0] = mm;
    }
    __syncthreads();
    m = red[0];
    __syncthreads();

    float s = 0.f;
    for (int i = t; i < VV; i += 1024) s += expf(g_logits[i] - m);
    s = warp_sum(s);
    if ((t & 31) == 0) red[t >> 5] = s;
    __syncthreads();
    if (t < 32) {
        float sv = red[t];
        sv = warp_sum(sv);
        if (t == 0) red[0] = m + logf(sv);
    }
    __syncthreads();
    const float lse = red[0];

    for (int i = blockIdx.x * 1024 + t; i < VV; i += gridDim.x * 1024)
        o_out[i] = g_logits[i] - lse;
}

// ---------------------------------------------------------------------------
extern "C" void kernel_launch(void* const* d_in, const int* in_sizes, int n_in,
                              void* d_out, int out_size) {
    const int*   word     = (const int*)  d_in[0];
    const float* last_ctx = (const float*)d_in[1];
    const float* last_hid = (const float*)d_in[2];
    const float* enc      = (const float*)d_in[3];
    const float* emb      = (const float*)d_in[4];
    const float* w_ih     = (const float*)d_in[5];
    const float* w_hh     = (const float*)d_in[6];
    const float* b_ih     = (const float*)d_in[7];
    const float* b_hh     = (const float*)d_in[8];
    const float* out_w    = (const float*)d_in[9];
    const float* out_b    = (const float*)d_in[10];

    float* out    = (float*)d_out;
    float* o_out  = out;                 // [V]   log_softmax output
    float* o_ctx  = out + VV;            // [H]   context
    float* o_hn   = out + VV + HD;       // [H]   h_new
    float* o_attn = out + VV + 2 * HD;   // [S]   attn

    k_gates<<<GG / 8, 256>>>(word, last_ctx, last_hid, emb, w_ih, w_hh, b_ih, b_hh);
    k_hnew_scores<<<SS / 32, 1024>>>(last_hid, enc, o_hn);
    k_attn_ctx<<<32, 256>>>(enc, o_attn);
    k_ctx_reduce<<<1, HD>>>(o_ctx);
    k_logits<<<(VV + 7) / 8, 256>>>(out_w, out_b, o_ctx);
    k_lse_out<<<32, 1024>>>(o_out);
}

// round 12
// speedup vs baseline: 1.1517x; 1.0896x over previous
#include <cuda_runtime.h>
#include <math.h>

#define HD 1024
#define VV 50257
#define SS 4096
#define GG 3072   // 3*H

// ---- scratch (no allocations allowed) ----
__device__ float g_gi[GG];
__device__ float g_gh[GG];
__device__ float g_hnew[HD];
__device__ float g_scores[SS];
__device__ float g_logits[VV];

__device__ __forceinline__ float warp_sum(float v) {
#pragma unroll
    for (int o = 16; o > 0; o >>= 1) v += __shfl_down_sync(0xffffffffu, v, o);
    return v;
}
__device__ __forceinline__ float warp_max(float v) {
#pragma unroll
    for (int o = 16; o > 0; o >>= 1) v = fmaxf(v, __shfl_down_sync(0xffffffffu, v, o));
    return v;
}

// ---------------------------------------------------------------------------
// K1: gi = w_ih @ [emb(word); last_ctx] + b_ih ; gh = w_hh @ h + b_hh
// one warp per output row (3072 rows), 8 warps/block
// ---------------------------------------------------------------------------
__global__ void __launch_bounds__(256)
k_gates(const int* __restrict__ word,
        const float* __restrict__ last_ctx,
        const float* __restrict__ last_hid,
        const float* __restrict__ emb,
        const float* __restrict__ w_ih,
        const float* __restrict__ w_hh,
        const float* __restrict__ b_ih,
        const float* __restrict__ b_hh) {
    __shared__ float sx[2 * HD];
    __shared__ float sh[HD];
    const int t = threadIdx.x;
    const int w = word[0];
    for (int i = t; i < HD; i += blockDim.x) {
        sx[i]      = emb[(size_t)w * HD + i];
        sx[HD + i] = last_ctx[i];
        sh[i]      = last_hid[i];
    }
    __syncthreads();

    const int lane = t & 31;
    const int row  = blockIdx.x * 8 + (t >> 5);

    const float4* wi4 = (const float4*)(w_ih + (size_t)row * 2 * HD);
    const float4* wh4 = (const float4*)(w_hh + (size_t)row * HD);
    const float4* sx4 = (const float4*)sx;
    const float4* sh4 = (const float4*)sh;

    float si = 0.f, sg = 0.f;
#pragma unroll 16
    for (int j = lane; j < 512; j += 32) {
        float4 a = wi4[j], b = sx4[j];
        si += a.x * b.x + a.y * b.y + a.z * b.z + a.w * b.w;
    }
#pragma unroll 8
    for (int j = lane; j < 256; j += 32) {
        float4 a = wh4[j], b = sh4[j];
        sg += a.x * b.x + a.y * b.y + a.z * b.z + a.w * b.w;
    }
    si = warp_sum(si);
    sg = warp_sum(sg);
    if (lane == 0) {
        g_gi[row] = si + b_ih[row];
        g_gh[row] = sg + b_hh[row];
    }
}

// ---------------------------------------------------------------------------
// K2: each block recomputes h_new (redundant, L2-cheap), then warp-per-s
//     computes scores[s] = enc[s,:] . h_new.  128 blocks x 1024 threads.
//     Block 0 publishes g_hnew and o_hn.
// ---------------------------------------------------------------------------
__global__ void __launch_bounds__(1024)
k_hnew_scores(const float* __restrict__ last_hid,
              const float* __restrict__ enc,
              float* __restrict__ o_hn) {
    __shared__ float sh[HD];
    const int t = threadIdx.x;

    // h_new (every block; identical values)
    {
        float r = 1.f / (1.f + expf(-(g_gi[t] + g_gh[t])));
        float z = 1.f / (1.f + expf(-(g_gi[HD + t] + g_gh[HD + t])));
        float n = tanhf(g_gi[2 * HD + t] + r * g_gh[2 * HD + t]);
        float h = last_hid[t];
        float hn = (1.f - z) * n + z * h;
        sh[t] = hn;
        if (blockIdx.x == 0) {
            g_hnew[t] = hn;
            o_hn[t]   = hn;
        }
    }
    __syncthreads();

    const int lane = t & 31;
    const int s    = blockIdx.x * 32 + (t >> 5);
    const float4* e4 = (const float4*)(enc + (size_t)s * HD);
    const float4* h4 = (const float4*)sh;
    float acc = 0.f;
#pragma unroll 8
    for (int j = lane; j < 256; j += 32) {
        float4 a = e4[j], b = h4[j];
        acc += a.x * b.x + a.y * b.y + a.z * b.z + a.w * b.w;
    }
    acc = warp_sum(acc);
    if (lane == 0) g_scores[s] = acc;
}

// ---------------------------------------------------------------------------
// K3: fused softmax + context (column-split, NO partial buffer / NO reduce
//     kernel).  32 blocks x 1024 threads.
//     Each block redundantly computes the softmax over all 4096 scores
//     (16 KB, L2-resident), then owns 32 columns of context:
//       warp w accumulates rows [w*128, w*128+128) for cols [b*32, b*32+32),
//       32x32 smem reduce, write o_ctx directly.
//     Block 0 also writes the full attn output (SCALAR stores — o_attn is
//     d_out + 52305 floats, not 16B-aligned; float4 stores fault).
// ---------------------------------------------------------------------------
__global__ void __launch_bounds__(1024)
k_attn_ctx(const float* __restrict__ enc,
           float* __restrict__ o_attn,
           float* __restrict__ o_ctx) {
    __shared__ float ss[SS];          // scores -> attn (16 KB)
    __shared__ float red[32];
    __shared__ float sred[32 * 32];   // per-warp column partials (4 KB)
    const int t = threadIdx.x;
    const int b = blockIdx.x;
    const int lane = t & 31;
    const int wrp  = t >> 5;

    // load all scores (one float4 per thread from aligned __device__ global)
    float4* ss4 = (float4*)ss;
    const float4* gs4 = (const float4*)g_scores;
    float4 v = gs4[t];
    ss4[t] = v;
    float m = fmaxf(fmaxf(v.x, v.y), fmaxf(v.z, v.w));
    m = warp_max(m);
    if (lane == 0) red[wrp] = m;
    __syncthreads();
    if (t < 32) {
        float mm = red[t];
        mm = warp_max(mm);
        if (t == 0) red[0] = mm;
    }
    __syncthreads();
    m = red[0];
    __syncthreads();

    // sum of exp
    float4 e;
    e.x = expf(v.x - m); e.y = expf(v.y - m);
    e.z = expf(v.z - m); e.w = expf(v.w - m);
    float s = e.x + e.y + e.z + e.w;
    s = warp_sum(s);
    if (lane == 0) red[wrp] = s;
    __syncthreads();
    if (t < 32) {
        float sv = red[t];
        sv = warp_sum(sv);
        if (t == 0) red[0] = sv;
    }
    __syncthreads();
    const float inv = 1.f / red[0];

    // attn into smem; block 0 publishes to output with scalar stores
    float4 a;
    a.x = e.x * inv; a.y = e.y * inv; a.z = e.z * inv; a.w = e.w * inv;
    ss4[t] = a;
    if (b == 0) {
        o_attn[4 * t + 0] = a.x;
        o_attn[4 * t + 1] = a.y;
        o_attn[4 * t + 2] = a.z;
        o_attn[4 * t + 3] = a.w;
    }
    __syncthreads();

    // context: this block owns cols [b*32, b*32+32).
    // warp w accumulates rows [w*128, w*128+128) for col = b*32+lane.
    const int col = b * 32 + lane;
    const float* ecol = enc + col;
    float acc = 0.f;
    const int r0 = wrp * 128;
#pragma unroll 8
    for (int r = r0; r < r0 + 128; r++) {
        acc += ss[r] * ecol[(size_t)r * HD];
    }
    sred[wrp * 32 + lane] = acc;
    __syncthreads();

    // reduce 32 warp-partials per column
    if (t < 32) {
        float sum = 0.f;
#pragma unroll
        for (int k = 0; k < 32; k++) sum += sred[k * 32 + t];
        o_ctx[b * 32 + t] = sum;
    }
}

// ---------------------------------------------------------------------------
// K4: logits = out_w @ [h_new ; context] + out_b   (warp per row, 50257 rows)
// ---------------------------------------------------------------------------
__global__ void __launch_bounds__(256)
k_logits(const float* __restrict__ out_w,
         const float* __restrict__ out_b,
         const float* __restrict__ o_ctx) {
    __shared__ float sx[2 * HD];
    const int t = threadIdx.x;
    for (int i = t; i < HD; i += blockDim.x) {
        sx[i]      = g_hnew[i];
        sx[HD + i] = o_ctx[i];
    }
    __syncthreads();

    const int lane = t & 31;
    const int row  = blockIdx.x * 8 + (t >> 5);
    if (row >= VV) return;

    const float4* w4  = (const float4*)(out_w + (size_t)row * 2 * HD);
    const float4* sx4 = (const float4*)sx;
    float acc = 0.f;
#pragma unroll 16
    for (int j = lane; j < 512; j += 32) {
        float4 a = w4[j], b = sx4[j];
        acc += a.x * b.x + a.y * b.y + a.z * b.z + a.w * b.w;
    }
    acc = warp_sum(acc);
    if (lane == 0) g_logits[row] = acc + out_b[row];
}

// ---------------------------------------------------------------------------
// K5: fused log-sum-exp + output.  32 blocks x 1024 threads.
//     Each block redundantly reduces over all 50257 logits (L2-resident),
//     then writes its strided slice of the output.
// ---------------------------------------------------------------------------
__global__ void __launch_bounds__(1024)
k_lse_out(float* __restrict__ o_out) {
    __shared__ float red[32];
    const int t = threadIdx.x;

    float m = -INFINITY;
    for (int i = t; i < VV; i += 1024) m = fmaxf(m, g_logits[i]);
    m = warp_max(m);
    if ((t & 31) == 0) red[t >> 5] = m;
    __syncthreads();
    if (t < 32) {
        float mm = red[t];
        mm = warp_max(mm);
        if (t == 0) red[0] = mm;
    }
    __syncthreads();
    m = red[0];
    __syncthreads();

    float s = 0.f;
    for (int i = t; i < VV; i += 1024) s += expf(g_logits[i] - m);
    s = warp_sum(s);
    if ((t & 31) == 0) red[t >> 5] = s;
    __syncthreads();
    if (t < 32) {
        float sv = red[t];
        sv = warp_sum(sv);
        if (t == 0) red[0] = m + logf(sv);
    }
    __syncthreads();
    const float lse = red[0];

    for (int i = blockIdx.x * 1024 + t; i < VV; i += gridDim.x * 1024)
        o_out[i] = g_logits[i] - lse;
}

// ---------------------------------------------------------------------------
extern "C" void kernel_launch(void* const* d_in, const int* in_sizes, int n_in,
                              void* d_out, int out_size) {
    const int*   word     = (const int*)  d_in[0];
    const float* last_ctx = (const float*)d_in[1];
    const float* last_hid = (const float*)d_in[2];
    const float* enc      = (const float*)d_in[3];
    const float* emb      = (const float*)d_in[4];
    const float* w_ih     = (const float*)d_in[5];
    const float* w_hh     = (const float*)d_in[6];
    const float* b_ih     = (const float*)d_in[7];
    const float* b_hh     = (const float*)d_in[8];
    const float* out_w    = (const float*)d_in[9];
    const float* out_b    = (const float*)d_in[10];

    float* out    = (float*)d_out;
    float* o_out  = out;                 // [V]   log_softmax output
    float* o_ctx  = out + VV;            // [H]   context
    float* o_hn   = out + VV + HD;       // [H]   h_new
    float* o_attn = out + VV + 2 * HD;   // [S]   attn

    k_gates<<<GG / 8, 256>>>(word, last_ctx, last_hid, emb, w_ih, w_hh, b_ih, b_hh);
    k_hnew_scores<<<SS / 32, 1024>>>(last_hid, enc, o_hn);
    k_attn_ctx<<<32, 1024>>>(enc, o_attn, o_ctx);
    k_logits<<<(VV + 7) / 8, 256>>>(out_w, out_b, o_ctx);
    k_lse_out<<<32, 1024>>>(o_out);
}